// round 5
// baseline (speedup 1.0000x reference)
#include <cuda_runtime.h>
#include <cuda_bf16.h>
#include <cstdint>
#include <cstddef>

#define EB 2048
#define SB 2048
#define BB 2
#define HH 16
#define DH 128
#define MTOT (BB*SB)

// ---------------- scratch (device globals; no allocation) ----------------
__device__ __nv_bfloat16 g_xh[(size_t)MTOT * EB];
__device__ __nv_bfloat16 g_xl[(size_t)MTOT * EB];
__device__ __nv_bfloat16 g_wh[(size_t)4 * EB * EB];
__device__ __nv_bfloat16 g_wl[(size_t)4 * EB * EB];
__device__ __nv_bfloat16 g_qh[(size_t)MTOT * EB];
__device__ __nv_bfloat16 g_ql[(size_t)MTOT * EB];
__device__ __nv_bfloat16 g_kh[(size_t)MTOT * EB];
__device__ __nv_bfloat16 g_kl[(size_t)MTOT * EB];
__device__ __nv_bfloat16 g_vh[(size_t)MTOT * EB];
__device__ __nv_bfloat16 g_vl[(size_t)MTOT * EB];
__device__ __nv_bfloat16 g_ch[(size_t)MTOT * EB];
__device__ __nv_bfloat16 g_cl[(size_t)MTOT * EB];

// ---------------- helpers ----------------
__device__ __forceinline__ uint32_t smem_u32(const void* p) {
    uint32_t a;
    asm("{ .reg .u64 t; cvta.to.shared.u64 t, %1; cvt.u32.u64 %0, t; }"
        : "=r"(a) : "l"(p));
    return a;
}

__device__ __forceinline__ void ldsm4(uint32_t* r, uint32_t a) {
    asm volatile("ldmatrix.sync.aligned.m8n8.x4.shared.b16 {%0,%1,%2,%3}, [%4];"
                 : "=r"(r[0]), "=r"(r[1]), "=r"(r[2]), "=r"(r[3]) : "r"(a));
}
__device__ __forceinline__ void ldsm4t(uint32_t* r, uint32_t a) {
    asm volatile("ldmatrix.sync.aligned.m8n8.x4.trans.shared.b16 {%0,%1,%2,%3}, [%4];"
                 : "=r"(r[0]), "=r"(r[1]), "=r"(r[2]), "=r"(r[3]) : "r"(a));
}

__device__ __forceinline__ void mma16816(float* d, const uint32_t* a, const uint32_t* b) {
    asm volatile(
        "mma.sync.aligned.m16n8k16.row.col.f32.bf16.bf16.f32 "
        "{%0,%1,%2,%3}, {%4,%5,%6,%7}, {%8,%9}, {%0,%1,%2,%3};"
        : "+f"(d[0]), "+f"(d[1]), "+f"(d[2]), "+f"(d[3])
        : "r"(a[0]), "r"(a[1]), "r"(a[2]), "r"(a[3]), "r"(b[0]), "r"(b[1]));
}

__device__ __forceinline__ void cp16(uint32_t dst, const void* src) {
    asm volatile("cp.async.cg.shared.global [%0], [%1], 16;" :: "r"(dst), "l"(src));
}
#define CP_COMMIT() asm volatile("cp.async.commit_group;" ::: "memory")
#define CP_WAIT1()  asm volatile("cp.async.wait_group 1;" ::: "memory")

__device__ __forceinline__ uint32_t pack_bf(float lo, float hi) {
    __nv_bfloat162 t = __float22bfloat162_rn(make_float2(lo, hi));
    return *reinterpret_cast<uint32_t*>(&t);
}
__device__ __forceinline__ float bf_round(float v) {
    return __bfloat162float(__float2bfloat16_rn(v));
}

// =========================================================================
// fp32 -> bf16 hi/lo split
// =========================================================================
__global__ void conv_split_kernel(const float* __restrict__ in,
                                  __nv_bfloat16* __restrict__ hi,
                                  __nv_bfloat16* __restrict__ lo, int n4)
{
    int i = blockIdx.x * blockDim.x + threadIdx.x;
    if (i >= n4) return;
    float4 v = reinterpret_cast<const float4*>(in)[i];
    float h0 = bf_round(v.x), h1 = bf_round(v.y), h2 = bf_round(v.z), h3 = bf_round(v.w);
    uint2 H, L;
    H.x = pack_bf(v.x, v.y); H.y = pack_bf(v.z, v.w);
    L.x = pack_bf(v.x - h0, v.y - h1); L.y = pack_bf(v.z - h2, v.w - h3);
    reinterpret_cast<uint2*>(hi)[i] = H;
    reinterpret_cast<uint2*>(lo)[i] = L;
}

// =========================================================================
// HMMA GEMM: C[M,N] = (Ah+Al)[M,K] @ (Bh+Bl)[N,K]^T + bias[N]
// 3-term split.  CTA 128x128, kc=32, 4 warps (2x2), warp tile 64x64.
// 128 threads, 2 CTAs/SM.
// =========================================================================
#define TM 128
#define TN 128
#define KC 32
#define GP 80                     // bytes/row in smem (64B data + 16B pad)
#define TILEB (128 * GP)          // 10240
#define STAGEB (4 * TILEB)        // 40960
#define GEMM_SMEM (2 * STAGEB)    // 81920

__device__ __forceinline__ void gemm_issue(
    const __nv_bfloat16* s0, const __nv_bfloat16* s1,
    const __nv_bfloat16* s2, const __nv_bfloat16* s3,
    int K, int k0, uint32_t base, int tid)
{
#pragma unroll
    for (int j = 0; j < 16; j++) {
        const int tile = j >> 2;
        const int part = (j & 3) * 128 + tid;   // 0..511
        const int r = part >> 2;
        const int c = part & 3;
        const __nv_bfloat16* g =
            (tile == 0 ? s0 : tile == 1 ? s1 : tile == 2 ? s2 : s3)
            + (size_t)r * K + k0 + c * 8;
        cp16(base + tile * TILEB + r * GP + c * 16, g);
    }
}

__global__ __launch_bounds__(128, 2)
void gemm_tc(const __nv_bfloat16* __restrict__ Ah, const __nv_bfloat16* __restrict__ Al,
             const __nv_bfloat16* __restrict__ Bh, const __nv_bfloat16* __restrict__ Bl,
             const float* __restrict__ bias,
             float* __restrict__ Cf,
             __nv_bfloat16* __restrict__ Ch, __nv_bfloat16* __restrict__ Cl,
             int M, int N, int K)
{
    extern __shared__ __align__(128) char smem[];
    const uint32_t sb = smem_u32(smem);
    const int tid = threadIdx.x, lane = tid & 31, wid = tid >> 5;
    const int wm = wid >> 1, wn = wid & 1;
    const int m0 = blockIdx.y * TM, n0 = blockIdx.x * TN;

    const __nv_bfloat16* s0 = Ah + (size_t)m0 * K;
    const __nv_bfloat16* s1 = Al + (size_t)m0 * K;
    const __nv_bfloat16* s2 = Bh + (size_t)n0 * K;
    const __nv_bfloat16* s3 = Bl + (size_t)n0 * K;

    gemm_issue(s0, s1, s2, s3, K, 0, sb, tid);            CP_COMMIT();
    gemm_issue(s0, s1, s2, s3, K, KC, sb + STAGEB, tid);  CP_COMMIT();

    float acc[4][8][4];
#pragma unroll
    for (int a = 0; a < 4; a++)
#pragma unroll
        for (int b = 0; b < 8; b++)
#pragma unroll
            for (int c = 0; c < 4; c++) acc[a][b][c] = 0.f;

    const int arow = wm * 64 + (lane & 15);
    const uint32_t ak8 = ((lane >> 4) << 3) * 2;
    const int brow = wn * 64 + ((lane >> 4) << 3) + (lane & 7);
    const uint32_t bk8 = (((lane >> 3) & 1) << 3) * 2;

    const int niter = K / KC;   // 64
    for (int it = 0; it < niter; ++it) {
        CP_WAIT1();
        __syncthreads();
        const uint32_t st = sb + (it & 1) * STAGEB;
        const uint32_t a_h = st, a_l = st + TILEB, b_h = st + 2 * TILEB, b_l = st + 3 * TILEB;
#pragma unroll
        for (int ks = 0; ks < 2; ++ks) {
            uint32_t ah[4][4], al[4][4];
            const uint32_t ao = ak8 + ks * 32;
#pragma unroll
            for (int mt = 0; mt < 4; mt++) {
                uint32_t ra = (uint32_t)(arow + mt * 16) * GP + ao;
                ldsm4(ah[mt], a_h + ra);
                ldsm4(al[mt], a_l + ra);
            }
#pragma unroll
            for (int nb = 0; nb < 4; nb++) {
                uint32_t bh[4], bl[4];
                uint32_t rb = (uint32_t)(brow + nb * 16) * GP + bk8 + ks * 32;
                ldsm4(bh, b_h + rb);
                ldsm4(bl, b_l + rb);
#pragma unroll
                for (int mt = 0; mt < 4; mt++) {
                    mma16816(acc[mt][2 * nb],     ah[mt], bh);
                    mma16816(acc[mt][2 * nb],     ah[mt], bl);
                    mma16816(acc[mt][2 * nb],     al[mt], bh);
                    mma16816(acc[mt][2 * nb + 1], ah[mt], bh + 2);
                    mma16816(acc[mt][2 * nb + 1], ah[mt], bl + 2);
                    mma16816(acc[mt][2 * nb + 1], al[mt], bh + 2);
                }
            }
        }
        __syncthreads();
        if (it + 2 < niter)
            gemm_issue(s0, s1, s2, s3, K, (it + 2) * KC, sb + (it & 1) * STAGEB, tid);
        CP_COMMIT();
    }

    // epilogue
    const int g = lane >> 2, q = lane & 3;
#pragma unroll
    for (int mt = 0; mt < 4; mt++) {
        const int r0 = m0 + wm * 64 + mt * 16 + g;
        const int r1 = r0 + 8;
#pragma unroll
        for (int nt = 0; nt < 8; nt++) {
            const int c = n0 + wn * 64 + nt * 8 + q * 2;
            const float b0 = __ldg(bias + c), b1 = __ldg(bias + c + 1);
            const float v00 = acc[mt][nt][0] + b0, v01 = acc[mt][nt][1] + b1;
            const float v10 = acc[mt][nt][2] + b0, v11 = acc[mt][nt][3] + b1;
            if (Cf) {
                *reinterpret_cast<float2*>(Cf + (size_t)r0 * N + c) = make_float2(v00, v01);
                *reinterpret_cast<float2*>(Cf + (size_t)r1 * N + c) = make_float2(v10, v11);
            } else {
                const float h00 = bf_round(v00), h01 = bf_round(v01);
                const float h10 = bf_round(v10), h11 = bf_round(v11);
                *reinterpret_cast<uint32_t*>(Ch + (size_t)r0 * N + c) = pack_bf(v00, v01);
                *reinterpret_cast<uint32_t*>(Cl + (size_t)r0 * N + c) = pack_bf(v00 - h00, v01 - h01);
                *reinterpret_cast<uint32_t*>(Ch + (size_t)r1 * N + c) = pack_bf(v10, v11);
                *reinterpret_cast<uint32_t*>(Cl + (size_t)r1 * N + c) = pack_bf(v10 - h10, v11 - h11);
            }
        }
    }
}

// =========================================================================
// Flash attention (causal), HMMA split-bf16, cp.async KV double-buffer.
// CTA: 128 q-rows x (b,h). 4 warps, warp owns 32 rows. KV tiles of 64.
// =========================================================================
#define AQ 128
#define AKV 64
#define AP 272                      // bytes/row (256B data + 16B pad)
#define QSZ (128 * AP)              // 34816 (one Q array)
#define KSZ (64 * AP)               // 17408 (one KV array)
#define AKVB (4 * KSZ)              // one KV stage: Kh,Kl,Vh,Vl = 69632
#define ATTN_SMEM (2 * QSZ + 2 * AKVB)   // 208896

__device__ __forceinline__ void attn_issue_kv(
    const __nv_bfloat16* khg, const __nv_bfloat16* klg,
    const __nv_bfloat16* vhg, const __nv_bfloat16* vlg,
    int kv0, uint32_t dst, int tid)
{
#pragma unroll
    for (int j = 0; j < 32; j++) {
        const int arr = j >> 3;
        const int part = (j & 7) * 128 + tid;   // 0..1023
        const int r = part >> 4;
        const int c = part & 15;
        const __nv_bfloat16* gp =
            (arr == 0 ? khg : arr == 1 ? klg : arr == 2 ? vhg : vlg)
            + (size_t)(kv0 + r) * EB + c * 8;
        cp16(dst + arr * KSZ + r * AP + c * 16, gp);
    }
}

__global__ __launch_bounds__(128, 1)
void attn_tc()
{
    extern __shared__ __align__(128) char smem[];
    const uint32_t sb = smem_u32(smem);
    const uint32_t QH = sb, QL = sb + QSZ, KVB = sb + 2 * QSZ;
    const int tid = threadIdx.x, lane = tid & 31, w = tid >> 5;
    const int qt = gridDim.x - 1 - blockIdx.x;      // big tiles first
    const int b  = blockIdx.y >> 4, h = blockIdx.y & 15;
    const int q0 = qt * AQ;
    const float scale = 0.08838834764831845f;       // 1/sqrt(128)

    const size_t hoff = (size_t)h * DH;
    const size_t bbase = (size_t)b * SB * EB + hoff;
    const __nv_bfloat16* qhg = g_qh + bbase + (size_t)q0 * EB;
    const __nv_bfloat16* qlg = g_ql + bbase + (size_t)q0 * EB;
    const __nv_bfloat16* khg = g_kh + bbase;
    const __nv_bfloat16* klg = g_kl + bbase;
    const __nv_bfloat16* vhg = g_vh + bbase;
    const __nv_bfloat16* vlg = g_vl + bbase;

    // prefetch Q (group 0), then KV tile 0 (group 1)
#pragma unroll
    for (int j = 0; j < 32; j++) {
        const int arr = j >> 4;
        const int part = (j & 15) * 128 + tid;   // 0..2047
        const int r = part >> 4;
        const int c = part & 15;
        const __nv_bfloat16* gp = (arr ? qlg : qhg) + (size_t)r * EB + c * 8;
        cp16((arr ? QL : QH) + r * AP + c * 16, gp);
    }
    CP_COMMIT();
    attn_issue_kv(khg, klg, vhg, vlg, 0, KVB, tid);
    CP_COMMIT();

    float o[2][16][4];
#pragma unroll
    for (int mt = 0; mt < 2; mt++)
#pragma unroll
        for (int i = 0; i < 16; i++)
#pragma unroll
            for (int j = 0; j < 4; j++) o[mt][i][j] = 0.f;
    float mrow[2][2], lrow[2][2];
#pragma unroll
    for (int mt = 0; mt < 2; mt++) {
        mrow[mt][0] = -1e30f; mrow[mt][1] = -1e30f;
        lrow[mt][0] = 0.f;    lrow[mt][1] = 0.f;
    }

    const int g = lane >> 2, q = lane & 3;
    const uint32_t a_k8 = ((lane >> 4) << 3) * 2;
    const int  k_row = ((lane >> 4) << 3) + (lane & 7);
    const uint32_t k_k8 = (((lane >> 3) & 1) << 3) * 2;
    const int  v_row = (((lane >> 3) & 1) << 3) + (lane & 7);
    const uint32_t v_d8 = ((lane >> 4) << 3) * 2;

    const int ntiles = 2 * qt + 2;
    for (int kti = 0; kti < ntiles; ++kti) {
        const int kv0 = kti * AKV;
        __syncthreads();   // prior readers done with stage we write next
        if (kti + 1 < ntiles)
            attn_issue_kv(khg, klg, vhg, vlg, (kti + 1) * AKV,
                          KVB + ((kti + 1) & 1) * AKVB, tid);
        CP_COMMIT();
        CP_WAIT1();        // tile kti (and Q on first iter) complete
        __syncthreads();

        if (kv0 > q0 + w * 32 + 31) continue;     // whole warp masked

        const uint32_t ST = KVB + (kti & 1) * AKVB;

        // ---- S = Q K^T  (32 q-rows x 64 kv) ----
        float s[2][8][4];
#pragma unroll
        for (int mt = 0; mt < 2; mt++)
#pragma unroll
            for (int i = 0; i < 8; i++)
#pragma unroll
                for (int j = 0; j < 4; j++) s[mt][i][j] = 0.f;

#pragma unroll
        for (int ks = 0; ks < 8; ks++) {
            uint32_t ah[2][4], al[2][4];
#pragma unroll
            for (int mt = 0; mt < 2; mt++) {
                const uint32_t ra = (uint32_t)(w * 32 + mt * 16 + (lane & 15)) * AP
                                    + a_k8 + ks * 32;
                ldsm4(ah[mt], QH + ra);
                ldsm4(al[mt], QL + ra);
            }
#pragma unroll
            for (int ntp = 0; ntp < 4; ntp++) {
                uint32_t bh[4], bl[4];
                const uint32_t ra = (uint32_t)(k_row + ntp * 16) * AP + k_k8 + ks * 32;
                ldsm4(bh, ST + 0 * KSZ + ra);
                ldsm4(bl, ST + 1 * KSZ + ra);
#pragma unroll
                for (int mt = 0; mt < 2; mt++) {
                    mma16816(s[mt][2 * ntp],     ah[mt], bh);
                    mma16816(s[mt][2 * ntp],     ah[mt], bl);
                    mma16816(s[mt][2 * ntp],     al[mt], bh);
                    mma16816(s[mt][2 * ntp + 1], ah[mt], bh + 2);
                    mma16816(s[mt][2 * ntp + 1], ah[mt], bl + 2);
                    mma16816(s[mt][2 * ntp + 1], al[mt], bh + 2);
                }
            }
        }

        // ---- scale + causal mask + online softmax per mt ----
        const bool needmask = (kv0 + AKV - 1) > (q0 + w * 32);
        float alpha[2][2];
#pragma unroll
        for (int mt = 0; mt < 2; mt++) {
            const int r0g = q0 + w * 32 + mt * 16 + g, r1g = r0g + 8;
#pragma unroll
            for (int nt = 0; nt < 8; nt++) {
                const int c0 = kv0 + nt * 8 + q * 2;
                s[mt][nt][0] *= scale; s[mt][nt][1] *= scale;
                s[mt][nt][2] *= scale; s[mt][nt][3] *= scale;
                if (needmask) {
                    if (c0     > r0g) s[mt][nt][0] = -1e30f;
                    if (c0 + 1 > r0g) s[mt][nt][1] = -1e30f;
                    if (c0     > r1g) s[mt][nt][2] = -1e30f;
                    if (c0 + 1 > r1g) s[mt][nt][3] = -1e30f;
                }
            }
            float mx0 = -1e30f, mx1 = -1e30f;
#pragma unroll
            for (int nt = 0; nt < 8; nt++) {
                mx0 = fmaxf(mx0, fmaxf(s[mt][nt][0], s[mt][nt][1]));
                mx1 = fmaxf(mx1, fmaxf(s[mt][nt][2], s[mt][nt][3]));
            }
            mx0 = fmaxf(mx0, __shfl_xor_sync(0xffffffffu, mx0, 1));
            mx0 = fmaxf(mx0, __shfl_xor_sync(0xffffffffu, mx0, 2));
            mx1 = fmaxf(mx1, __shfl_xor_sync(0xffffffffu, mx1, 1));
            mx1 = fmaxf(mx1, __shfl_xor_sync(0xffffffffu, mx1, 2));

            const float mn0 = fmaxf(mrow[mt][0], mx0), mn1 = fmaxf(mrow[mt][1], mx1);
            alpha[mt][0] = __expf(mrow[mt][0] - mn0);
            alpha[mt][1] = __expf(mrow[mt][1] - mn1);
            mrow[mt][0] = mn0; mrow[mt][1] = mn1;
            float rs0 = 0.f, rs1 = 0.f;
#pragma unroll
            for (int nt = 0; nt < 8; nt++) {
                s[mt][nt][0] = __expf(s[mt][nt][0] - mn0); rs0 += s[mt][nt][0];
                s[mt][nt][1] = __expf(s[mt][nt][1] - mn0); rs0 += s[mt][nt][1];
                s[mt][nt][2] = __expf(s[mt][nt][2] - mn1); rs1 += s[mt][nt][2];
                s[mt][nt][3] = __expf(s[mt][nt][3] - mn1); rs1 += s[mt][nt][3];
            }
            rs0 += __shfl_xor_sync(0xffffffffu, rs0, 1);
            rs0 += __shfl_xor_sync(0xffffffffu, rs0, 2);
            rs1 += __shfl_xor_sync(0xffffffffu, rs1, 1);
            rs1 += __shfl_xor_sync(0xffffffffu, rs1, 2);
            lrow[mt][0] = lrow[mt][0] * alpha[mt][0] + rs0;
            lrow[mt][1] = lrow[mt][1] * alpha[mt][1] + rs1;
#pragma unroll
            for (int nt = 0; nt < 16; nt++) {
                o[mt][nt][0] *= alpha[mt][0]; o[mt][nt][1] *= alpha[mt][0];
                o[mt][nt][2] *= alpha[mt][1]; o[mt][nt][3] *= alpha[mt][1];
            }
        }

        // ---- O += P @ V ----
#pragma unroll
        for (int kt = 0; kt < 4; kt++) {
            uint32_t ph[2][4], pl[2][4];
#pragma unroll
            for (int mt = 0; mt < 2; mt++) {
                const float* p0 = s[mt][2 * kt];
                const float* p1 = s[mt][2 * kt + 1];
                ph[mt][0] = pack_bf(p0[0], p0[1]);
                ph[mt][1] = pack_bf(p0[2], p0[3]);
                ph[mt][2] = pack_bf(p1[0], p1[1]);
                ph[mt][3] = pack_bf(p1[2], p1[3]);
                pl[mt][0] = pack_bf(p0[0] - bf_round(p0[0]), p0[1] - bf_round(p0[1]));
                pl[mt][1] = pack_bf(p0[2] - bf_round(p0[2]), p0[3] - bf_round(p0[3]));
                pl[mt][2] = pack_bf(p1[0] - bf_round(p1[0]), p1[1] - bf_round(p1[1]));
                pl[mt][3] = pack_bf(p1[2] - bf_round(p1[2]), p1[3] - bf_round(p1[3]));
            }
#pragma unroll
            for (int np = 0; np < 8; np++) {
                uint32_t bh[4], bl[4];
                const uint32_t ra = (uint32_t)(v_row + kt * 16) * AP + v_d8 + np * 32;
                ldsm4t(bh, ST + 2 * KSZ + ra);
                ldsm4t(bl, ST + 3 * KSZ + ra);
#pragma unroll
                for (int mt = 0; mt < 2; mt++) {
                    mma16816(o[mt][2 * np],     ph[mt], bh);
                    mma16816(o[mt][2 * np],     ph[mt], bl);
                    mma16816(o[mt][2 * np],     pl[mt], bh);
                    mma16816(o[mt][2 * np + 1], ph[mt], bh + 2);
                    mma16816(o[mt][2 * np + 1], ph[mt], bl + 2);
                    mma16816(o[mt][2 * np + 1], pl[mt], bh + 2);
                }
            }
        }
    }

    // ---- normalize + write split-bf16 ctx ----
#pragma unroll
    for (int mt = 0; mt < 2; mt++) {
        const float inv0 = 1.f / lrow[mt][0], inv1 = 1.f / lrow[mt][1];
        const int r0g = q0 + w * 32 + mt * 16 + g;
        const size_t base0 = ((size_t)b * SB + r0g) * EB + hoff;
        const size_t base1 = base0 + (size_t)8 * EB;
#pragma unroll
        for (int nt = 0; nt < 16; nt++) {
            const int c = nt * 8 + q * 2;
            const float v00 = o[mt][nt][0] * inv0, v01 = o[mt][nt][1] * inv0;
            const float v10 = o[mt][nt][2] * inv1, v11 = o[mt][nt][3] * inv1;
            const float h00 = bf_round(v00), h01 = bf_round(v01);
            const float h10 = bf_round(v10), h11 = bf_round(v11);
            *reinterpret_cast<uint32_t*>(g_ch + base0 + c) = pack_bf(v00, v01);
            *reinterpret_cast<uint32_t*>(g_cl + base0 + c) = pack_bf(v00 - h00, v01 - h01);
            *reinterpret_cast<uint32_t*>(g_ch + base1 + c) = pack_bf(v10, v11);
            *reinterpret_cast<uint32_t*>(g_cl + base1 + c) = pack_bf(v10 - h10, v11 - h11);
        }
    }
}

// =========================================================================
extern "C" void kernel_launch(void* const* d_in, const int* in_sizes, int n_in,
                              void* d_out, int out_size)
{
    const float* x  = (const float*)d_in[0];
    const float* Wq = (const float*)d_in[1];
    const float* bq = (const float*)d_in[2];
    const float* Wk = (const float*)d_in[3];
    const float* bk = (const float*)d_in[4];
    const float* Wv = (const float*)d_in[5];
    const float* bv = (const float*)d_in[6];
    const float* Wo = (const float*)d_in[7];
    const float* bo = (const float*)d_in[8];
    float* out = (float*)d_out;

    __nv_bfloat16 *xh, *xl, *wh, *wl, *qh, *ql, *kh, *kl, *vh, *vl, *ch, *cl;
    cudaGetSymbolAddress((void**)&xh, g_xh);
    cudaGetSymbolAddress((void**)&xl, g_xl);
    cudaGetSymbolAddress((void**)&wh, g_wh);
    cudaGetSymbolAddress((void**)&wl, g_wl);
    cudaGetSymbolAddress((void**)&qh, g_qh);
    cudaGetSymbolAddress((void**)&ql, g_ql);
    cudaGetSymbolAddress((void**)&kh, g_kh);
    cudaGetSymbolAddress((void**)&kl, g_kl);
    cudaGetSymbolAddress((void**)&vh, g_vh);
    cudaGetSymbolAddress((void**)&vl, g_vl);
    cudaGetSymbolAddress((void**)&ch, g_ch);
    cudaGetSymbolAddress((void**)&cl, g_cl);

    cudaFuncSetAttribute(gemm_tc, cudaFuncAttributeMaxDynamicSharedMemorySize, GEMM_SMEM);
    cudaFuncSetAttribute(attn_tc, cudaFuncAttributeMaxDynamicSharedMemorySize, ATTN_SMEM);

    const size_t WN = (size_t)EB * EB;
    const int xn4 = (MTOT * EB) / 4;
    const int wn4 = (int)(WN / 4);

    conv_split_kernel<<<(xn4 + 255) / 256, 256>>>(x, xh, xl, xn4);
    conv_split_kernel<<<(wn4 + 255) / 256, 256>>>(Wq, wh + 0 * WN, wl + 0 * WN, wn4);
    conv_split_kernel<<<(wn4 + 255) / 256, 256>>>(Wk, wh + 1 * WN, wl + 1 * WN, wn4);
    conv_split_kernel<<<(wn4 + 255) / 256, 256>>>(Wv, wh + 2 * WN, wl + 2 * WN, wn4);
    conv_split_kernel<<<(wn4 + 255) / 256, 256>>>(Wo, wh + 3 * WN, wl + 3 * WN, wn4);

    dim3 ggrid(EB / TN, MTOT / TM);   // (16, 32)
    gemm_tc<<<ggrid, 128, GEMM_SMEM>>>(xh, xl, wh + 0 * WN, wl + 0 * WN, bq,
                                       nullptr, qh, ql, MTOT, EB, EB);
    gemm_tc<<<ggrid, 128, GEMM_SMEM>>>(xh, xl, wh + 1 * WN, wl + 1 * WN, bk,
                                       nullptr, kh, kl, MTOT, EB, EB);
    gemm_tc<<<ggrid, 128, GEMM_SMEM>>>(xh, xl, wh + 2 * WN, wl + 2 * WN, bv,
                                       nullptr, vh, vl, MTOT, EB, EB);

    attn_tc<<<dim3(SB / AQ, BB * HH), 128, ATTN_SMEM>>>();

    gemm_tc<<<ggrid, 128, GEMM_SMEM>>>(ch, cl, wh + 3 * WN, wl + 3 * WN, bo,
                                       out, nullptr, nullptr, MTOT, EB, EB);
}

// round 6
// speedup vs baseline: 1.5959x; 1.5959x over previous
#include <cuda_runtime.h>
#include <cuda_fp16.h>
#include <cstdint>
#include <cstddef>

#define EB 2048
#define SB 2048
#define BB 2
#define HH 16
#define DH 128
#define MTOT (BB*SB)

// ---------------- scratch (device globals; no allocation) ----------------
__device__ __half g_xh[(size_t)MTOT * EB];
__device__ __half g_xl[(size_t)MTOT * EB];
__device__ __half g_w[(size_t)4 * EB * EB];
__device__ __half g_q[(size_t)MTOT * EB];
__device__ __half g_k[(size_t)MTOT * EB];
__device__ __half g_vh[(size_t)MTOT * EB];
__device__ __half g_vl[(size_t)MTOT * EB];
__device__ __half g_ch[(size_t)MTOT * EB];
__device__ __half g_cl[(size_t)MTOT * EB];

// ---------------- helpers ----------------
__device__ __forceinline__ uint32_t smem_u32(const void* p) {
    uint32_t a;
    asm("{ .reg .u64 t; cvta.to.shared.u64 t, %1; cvt.u32.u64 %0, t; }"
        : "=r"(a) : "l"(p));
    return a;
}

__device__ __forceinline__ void ldsm4(uint32_t* r, uint32_t a) {
    asm volatile("ldmatrix.sync.aligned.m8n8.x4.shared.b16 {%0,%1,%2,%3}, [%4];"
                 : "=r"(r[0]), "=r"(r[1]), "=r"(r[2]), "=r"(r[3]) : "r"(a));
}
__device__ __forceinline__ void ldsm4t(uint32_t* r, uint32_t a) {
    asm volatile("ldmatrix.sync.aligned.m8n8.x4.trans.shared.b16 {%0,%1,%2,%3}, [%4];"
                 : "=r"(r[0]), "=r"(r[1]), "=r"(r[2]), "=r"(r[3]) : "r"(a));
}

__device__ __forceinline__ void mma16816(float* d, const uint32_t* a, const uint32_t* b) {
    asm volatile(
        "mma.sync.aligned.m16n8k16.row.col.f32.f16.f16.f32 "
        "{%0,%1,%2,%3}, {%4,%5,%6,%7}, {%8,%9}, {%0,%1,%2,%3};"
        : "+f"(d[0]), "+f"(d[1]), "+f"(d[2]), "+f"(d[3])
        : "r"(a[0]), "r"(a[1]), "r"(a[2]), "r"(a[3]), "r"(b[0]), "r"(b[1]));
}

__device__ __forceinline__ void cp16(uint32_t dst, const void* src) {
    asm volatile("cp.async.cg.shared.global [%0], [%1], 16;" :: "r"(dst), "l"(src));
}
#define CP_COMMIT() asm volatile("cp.async.commit_group;" ::: "memory")
#define CP_WAIT1()  asm volatile("cp.async.wait_group 1;" ::: "memory")

__device__ __forceinline__ uint32_t pack_h(float lo, float hi) {
    __half2 t = __floats2half2_rn(lo, hi);
    return *reinterpret_cast<uint32_t*>(&t);
}
__device__ __forceinline__ float h_round(float v) {
    return __half2float(__float2half_rn(v));
}

// =========================================================================
// fp32 -> fp16 hi/lo split  (exact pair: hi + lo reproduces fp32 to ~u^2)
// =========================================================================
__global__ void conv_split_kernel(const float* __restrict__ in,
                                  __half* __restrict__ hi,
                                  __half* __restrict__ lo, int n4)
{
    int i = blockIdx.x * blockDim.x + threadIdx.x;
    if (i >= n4) return;
    float4 v = reinterpret_cast<const float4*>(in)[i];
    float h0 = h_round(v.x), h1 = h_round(v.y), h2 = h_round(v.z), h3 = h_round(v.w);
    uint2 H, L;
    H.x = pack_h(v.x, v.y); H.y = pack_h(v.z, v.w);
    L.x = pack_h(v.x - h0, v.y - h1); L.y = pack_h(v.z - h2, v.w - h3);
    reinterpret_cast<uint2*>(hi)[i] = H;
    reinterpret_cast<uint2*>(lo)[i] = L;
}

// fp32 -> fp16 single cast (weights)
__global__ void conv_cast_kernel(const float* __restrict__ in,
                                 __half* __restrict__ out, int n4)
{
    int i = blockIdx.x * blockDim.x + threadIdx.x;
    if (i >= n4) return;
    float4 v = reinterpret_cast<const float4*>(in)[i];
    uint2 H;
    H.x = pack_h(v.x, v.y); H.y = pack_h(v.z, v.w);
    reinterpret_cast<uint2*>(out)[i] = H;
}

// =========================================================================
// HMMA GEMM: C[M,N] = (Ah+Al)[M,K] @ B[N,K]^T + bias[N]
// A exact fp16 pair, B single fp16 -> 2 mma per logical mma.
// CTA 128x128, kc=32, 8 warps (2x4), warp tile 64x32, 2 CTAs/SM.
// Output modes: Cf (fp32) | Ch+Cl (split fp16) | Ch only (single fp16).
// =========================================================================
#define TM 128
#define TN 128
#define KC 32
#define GP 80                     // bytes/row in smem (64B data + 16B pad)
#define TILEB (128 * GP)          // 10240
#define STAGEB (3 * TILEB)        // Ah, Al, B = 30720
#define GEMM_SMEM (2 * STAGEB)    // 61440

__device__ __forceinline__ void gemm_issue(
    const __half* s0, const __half* s1, const __half* s2,
    int K, int k0, uint32_t base, int tid)
{
#pragma unroll
    for (int j = 0; j < 6; j++) {
        const int tile = j >> 1;
        const int part = (j & 1) * 256 + tid;   // 0..511
        const int r = part >> 2;
        const int c = part & 3;
        const __half* g =
            (tile == 0 ? s0 : tile == 1 ? s1 : s2)
            + (size_t)r * K + k0 + c * 8;
        cp16(base + tile * TILEB + r * GP + c * 16, g);
    }
}

__global__ __launch_bounds__(256, 2)
void gemm_tc(const __half* __restrict__ Ah, const __half* __restrict__ Al,
             const __half* __restrict__ B,
             const float* __restrict__ bias,
             float* __restrict__ Cf,
             __half* __restrict__ Ch, __half* __restrict__ Cl,
             int M, int N, int K)
{
    extern __shared__ __align__(128) char smem[];
    const uint32_t sb = smem_u32(smem);
    const int tid = threadIdx.x, lane = tid & 31, wid = tid >> 5;
    const int wm = wid >> 2, wn = wid & 3;
    const int m0 = blockIdx.y * TM, n0 = blockIdx.x * TN;

    const __half* s0 = Ah + (size_t)m0 * K;
    const __half* s1 = Al + (size_t)m0 * K;
    const __half* s2 = B  + (size_t)n0 * K;

    gemm_issue(s0, s1, s2, K, 0, sb, tid);            CP_COMMIT();
    gemm_issue(s0, s1, s2, K, KC, sb + STAGEB, tid);  CP_COMMIT();

    float acc[4][4][4];
#pragma unroll
    for (int a = 0; a < 4; a++)
#pragma unroll
        for (int b = 0; b < 4; b++)
#pragma unroll
            for (int c = 0; c < 4; c++) acc[a][b][c] = 0.f;

    const int arow = wm * 64 + (lane & 15);
    const uint32_t ak8 = ((lane >> 4) << 3) * 2;
    const int brow = wn * 32 + ((lane >> 4) << 3) + (lane & 7);
    const uint32_t bk8 = (((lane >> 3) & 1) << 3) * 2;

    const int niter = K / KC;   // 64
    for (int it = 0; it < niter; ++it) {
        CP_WAIT1();
        __syncthreads();
        const uint32_t st = sb + (it & 1) * STAGEB;
        const uint32_t a_h = st, a_l = st + TILEB, b_s = st + 2 * TILEB;
#pragma unroll
        for (int ks = 0; ks < 2; ++ks) {
            uint32_t ah[4][4], al[4][4];
            const uint32_t ao = ak8 + ks * 32;
#pragma unroll
            for (int mt = 0; mt < 4; mt++) {
                uint32_t ra = (uint32_t)(arow + mt * 16) * GP + ao;
                ldsm4(ah[mt], a_h + ra);
                ldsm4(al[mt], a_l + ra);
            }
#pragma unroll
            for (int np = 0; np < 2; np++) {
                uint32_t bh[4];
                uint32_t rb = (uint32_t)(brow + np * 16) * GP + bk8 + ks * 32;
                ldsm4(bh, b_s + rb);
#pragma unroll
                for (int mt = 0; mt < 4; mt++) {
                    mma16816(acc[mt][2 * np],     ah[mt], bh);
                    mma16816(acc[mt][2 * np],     al[mt], bh);
                    mma16816(acc[mt][2 * np + 1], ah[mt], bh + 2);
                    mma16816(acc[mt][2 * np + 1], al[mt], bh + 2);
                }
            }
        }
        __syncthreads();
        if (it + 2 < niter)
            gemm_issue(s0, s1, s2, K, (it + 2) * KC, sb + (it & 1) * STAGEB, tid);
        CP_COMMIT();
    }

    // epilogue
    const int g = lane >> 2, q = lane & 3;
#pragma unroll
    for (int mt = 0; mt < 4; mt++) {
        const int r0 = m0 + wm * 64 + mt * 16 + g;
        const int r1 = r0 + 8;
#pragma unroll
        for (int nt = 0; nt < 4; nt++) {
            const int c = n0 + wn * 32 + nt * 8 + q * 2;
            const float b0 = __ldg(bias + c), b1 = __ldg(bias + c + 1);
            const float v00 = acc[mt][nt][0] + b0, v01 = acc[mt][nt][1] + b1;
            const float v10 = acc[mt][nt][2] + b0, v11 = acc[mt][nt][3] + b1;
            if (Cf) {
                *reinterpret_cast<float2*>(Cf + (size_t)r0 * N + c) = make_float2(v00, v01);
                *reinterpret_cast<float2*>(Cf + (size_t)r1 * N + c) = make_float2(v10, v11);
            } else if (Cl) {
                const float h00 = h_round(v00), h01 = h_round(v01);
                const float h10 = h_round(v10), h11 = h_round(v11);
                *reinterpret_cast<uint32_t*>(Ch + (size_t)r0 * N + c) = pack_h(v00, v01);
                *reinterpret_cast<uint32_t*>(Cl + (size_t)r0 * N + c) = pack_h(v00 - h00, v01 - h01);
                *reinterpret_cast<uint32_t*>(Ch + (size_t)r1 * N + c) = pack_h(v10, v11);
                *reinterpret_cast<uint32_t*>(Cl + (size_t)r1 * N + c) = pack_h(v10 - h10, v11 - h11);
            } else {
                *reinterpret_cast<uint32_t*>(Ch + (size_t)r0 * N + c) = pack_h(v00, v01);
                *reinterpret_cast<uint32_t*>(Ch + (size_t)r1 * N + c) = pack_h(v10, v11);
            }
        }
    }
}

// =========================================================================
// Flash attention (causal), fp16 HMMA, cp.async KV double-buffer.
// Q,K,P single fp16; V exact split (vh+vl). CTA: 128 q x (b,h), 8 warps.
// =========================================================================
#define AQ 128
#define AKV 64
#define AP 272                      // bytes/row (256B data + 16B pad)
#define QSZ (128 * AP)              // 34816
#define KSZ (64 * AP)               // 17408
#define AKVB (3 * KSZ)              // one KV stage: K, Vh, Vl = 52224
#define ATTN_SMEM (QSZ + 2 * AKVB)  // 139264

__device__ __forceinline__ void attn_issue_kv(
    const __half* kg, const __half* vhg, const __half* vlg,
    int kv0, uint32_t dst, int tid)
{
#pragma unroll
    for (int j = 0; j < 12; j++) {
        const int arr = j >> 2;
        const int part = (j & 3) * 256 + tid;   // 0..1023
        const int r = part >> 4;
        const int c = part & 15;
        const __half* gp =
            (arr == 0 ? kg : arr == 1 ? vhg : vlg)
            + (size_t)(kv0 + r) * EB + c * 8;
        cp16(dst + arr * KSZ + r * AP + c * 16, gp);
    }
}

__global__ __launch_bounds__(256, 1)
void attn_tc()
{
    extern __shared__ __align__(128) char smem[];
    const uint32_t sb = smem_u32(smem);
    const uint32_t QS = sb, KVB = sb + QSZ;
    const int tid = threadIdx.x, lane = tid & 31, w = tid >> 5;
    const int qt = gridDim.x - 1 - blockIdx.x;      // big tiles first
    const int b  = blockIdx.y >> 4, h = blockIdx.y & 15;
    const int q0 = qt * AQ;
    const float scale = 0.08838834764831845f;       // 1/sqrt(128)

    const size_t hoff = (size_t)h * DH;
    const size_t bbase = (size_t)b * SB * EB + hoff;
    const __half* qg  = g_q  + bbase + (size_t)q0 * EB;
    const __half* kg  = g_k  + bbase;
    const __half* vhg = g_vh + bbase;
    const __half* vlg = g_vl + bbase;

    // prefetch KV tile 0 (stage 0)
    attn_issue_kv(kg, vhg, vlg, 0, KVB, tid);
    CP_COMMIT();

    // load Q (128 x 128 fp16) — overlaps with the cp.async above
#pragma unroll
    for (int j = 0; j < 8; j++) {
        const int part = j * 256 + tid;   // 0..2047
        const int r = part >> 4;
        const int c = part & 15;
        uint4 v = *reinterpret_cast<const uint4*>(qg + (size_t)r * EB + c * 8);
        *reinterpret_cast<uint4*>(smem + r * AP + c * 16) = v;
    }

    float o[16][4];
#pragma unroll
    for (int i = 0; i < 16; i++)
#pragma unroll
        for (int j = 0; j < 4; j++) o[i][j] = 0.f;
    float m0v = -1e30f, m1v = -1e30f, l0 = 0.f, l1 = 0.f;

    const int g = lane >> 2, q = lane & 3;
    const uint32_t a_row = (uint32_t)(w * 16 + (lane & 15)) * AP;
    const uint32_t a_k8  = ((lane >> 4) << 3) * 2;
    const int  k_row = ((lane >> 4) << 3) + (lane & 7);
    const uint32_t k_k8 = (((lane >> 3) & 1) << 3) * 2;
    const int  v_row = (((lane >> 3) & 1) << 3) + (lane & 7);
    const uint32_t v_d8 = ((lane >> 4) << 3) * 2;

    const int ntiles = 2 * qt + 2;
    for (int kti = 0; kti < ntiles; ++kti) {
        const int kv0 = kti * AKV;
        __syncthreads();   // all readers done with the stage we write next
        if (kti + 1 < ntiles)
            attn_issue_kv(kg, vhg, vlg, (kti + 1) * AKV,
                          KVB + ((kti + 1) & 1) * AKVB, tid);
        CP_COMMIT();
        CP_WAIT1();        // tile kti complete
        __syncthreads();

        if (kv0 > q0 + w * 16 + 15) continue;     // whole warp masked

        const uint32_t ST = KVB + (kti & 1) * AKVB;

        // ---- S = Q K^T  (single fp16 both sides) ----
        float s[8][4];
#pragma unroll
        for (int i = 0; i < 8; i++)
#pragma unroll
            for (int j = 0; j < 4; j++) s[i][j] = 0.f;

#pragma unroll
        for (int ks = 0; ks < 8; ks++) {
            uint32_t aq[4];
            ldsm4(aq, QS + a_row + a_k8 + ks * 32);
#pragma unroll
            for (int ntp = 0; ntp < 4; ntp++) {
                uint32_t bh[4];
                const uint32_t ra = (uint32_t)(k_row + ntp * 16) * AP + k_k8 + ks * 32;
                ldsm4(bh, ST + ra);
                mma16816(s[2 * ntp],     aq, bh);
                mma16816(s[2 * ntp + 1], aq, bh + 2);
            }
        }

        // ---- scale + causal mask ----
        const int r0g = q0 + w * 16 + g, r1g = r0g + 8;
        const bool needmask = (kv0 + AKV - 1) > (q0 + w * 16);
#pragma unroll
        for (int nt = 0; nt < 8; nt++) {
            const int c0 = kv0 + nt * 8 + q * 2;
            s[nt][0] *= scale; s[nt][1] *= scale; s[nt][2] *= scale; s[nt][3] *= scale;
            if (needmask) {
                if (c0     > r0g) s[nt][0] = -1e30f;
                if (c0 + 1 > r0g) s[nt][1] = -1e30f;
                if (c0     > r1g) s[nt][2] = -1e30f;
                if (c0 + 1 > r1g) s[nt][3] = -1e30f;
            }
        }

        // ---- online softmax (rows r0g, r1g) ----
        float mx0 = -1e30f, mx1 = -1e30f;
#pragma unroll
        for (int nt = 0; nt < 8; nt++) {
            mx0 = fmaxf(mx0, fmaxf(s[nt][0], s[nt][1]));
            mx1 = fmaxf(mx1, fmaxf(s[nt][2], s[nt][3]));
        }
        mx0 = fmaxf(mx0, __shfl_xor_sync(0xffffffffu, mx0, 1));
        mx0 = fmaxf(mx0, __shfl_xor_sync(0xffffffffu, mx0, 2));
        mx1 = fmaxf(mx1, __shfl_xor_sync(0xffffffffu, mx1, 1));
        mx1 = fmaxf(mx1, __shfl_xor_sync(0xffffffffu, mx1, 2));

        const float mn0 = fmaxf(m0v, mx0), mn1 = fmaxf(m1v, mx1);
        const float al0 = __expf(m0v - mn0), al1 = __expf(m1v - mn1);
        m0v = mn0; m1v = mn1;
        float rs0 = 0.f, rs1 = 0.f;
#pragma unroll
        for (int nt = 0; nt < 8; nt++) {
            s[nt][0] = __expf(s[nt][0] - mn0); rs0 += s[nt][0];
            s[nt][1] = __expf(s[nt][1] - mn0); rs0 += s[nt][1];
            s[nt][2] = __expf(s[nt][2] - mn1); rs1 += s[nt][2];
            s[nt][3] = __expf(s[nt][3] - mn1); rs1 += s[nt][3];
        }
        rs0 += __shfl_xor_sync(0xffffffffu, rs0, 1);
        rs0 += __shfl_xor_sync(0xffffffffu, rs0, 2);
        rs1 += __shfl_xor_sync(0xffffffffu, rs1, 1);
        rs1 += __shfl_xor_sync(0xffffffffu, rs1, 2);
        l0 = l0 * al0 + rs0;
        l1 = l1 * al1 + rs1;
#pragma unroll
        for (int nt = 0; nt < 16; nt++) {
            o[nt][0] *= al0; o[nt][1] *= al0; o[nt][2] *= al1; o[nt][3] *= al1;
        }

        // ---- O += P @ (Vh + Vl)  (P single fp16, V exact split) ----
#pragma unroll
        for (int kt = 0; kt < 4; kt++) {
            uint32_t ph[4];
            const float* p0 = s[2 * kt];
            const float* p1 = s[2 * kt + 1];
            ph[0] = pack_h(p0[0], p0[1]);
            ph[1] = pack_h(p0[2], p0[3]);
            ph[2] = pack_h(p1[0], p1[1]);
            ph[3] = pack_h(p1[2], p1[3]);
#pragma unroll
            for (int np = 0; np < 8; np++) {
                uint32_t vh[4], vl[4];
                const uint32_t ra = (uint32_t)(v_row + kt * 16) * AP + v_d8 + np * 32;
                ldsm4t(vh, ST + 1 * KSZ + ra);
                ldsm4t(vl, ST + 2 * KSZ + ra);
                mma16816(o[2 * np],     ph, vh);
                mma16816(o[2 * np],     ph, vl);
                mma16816(o[2 * np + 1], ph, vh + 2);
                mma16816(o[2 * np + 1], ph, vl + 2);
            }
        }
    }

    // ---- normalize + write split-fp16 ctx ----
    const float inv0 = 1.f / l0, inv1 = 1.f / l1;
    const int r0g = q0 + w * 16 + g;
    const size_t base0 = ((size_t)b * SB + r0g) * EB + hoff;
    const size_t base1 = base0 + (size_t)8 * EB;
#pragma unroll
    for (int nt = 0; nt < 16; nt++) {
        const int c = nt * 8 + q * 2;
        const float v00 = o[nt][0] * inv0, v01 = o[nt][1] * inv0;
        const float v10 = o[nt][2] * inv1, v11 = o[nt][3] * inv1;
        const float h00 = h_round(v00), h01 = h_round(v01);
        const float h10 = h_round(v10), h11 = h_round(v11);
        *reinterpret_cast<uint32_t*>(g_ch + base0 + c) = pack_h(v00, v01);
        *reinterpret_cast<uint32_t*>(g_cl + base0 + c) = pack_h(v00 - h00, v01 - h01);
        *reinterpret_cast<uint32_t*>(g_ch + base1 + c) = pack_h(v10, v11);
        *reinterpret_cast<uint32_t*>(g_cl + base1 + c) = pack_h(v10 - h10, v11 - h11);
    }
}

// =========================================================================
extern "C" void kernel_launch(void* const* d_in, const int* in_sizes, int n_in,
                              void* d_out, int out_size)
{
    const float* x  = (const float*)d_in[0];
    const float* Wq = (const float*)d_in[1];
    const float* bq = (const float*)d_in[2];
    const float* Wk = (const float*)d_in[3];
    const float* bk = (const float*)d_in[4];
    const float* Wv = (const float*)d_in[5];
    const float* bv = (const float*)d_in[6];
    const float* Wo = (const float*)d_in[7];
    const float* bo = (const float*)d_in[8];
    float* out = (float*)d_out;

    __half *xh, *xl, *wp, *qp, *kp, *vh, *vl, *ch, *cl;
    cudaGetSymbolAddress((void**)&xh, g_xh);
    cudaGetSymbolAddress((void**)&xl, g_xl);
    cudaGetSymbolAddress((void**)&wp, g_w);
    cudaGetSymbolAddress((void**)&qp, g_q);
    cudaGetSymbolAddress((void**)&kp, g_k);
    cudaGetSymbolAddress((void**)&vh, g_vh);
    cudaGetSymbolAddress((void**)&vl, g_vl);
    cudaGetSymbolAddress((void**)&ch, g_ch);
    cudaGetSymbolAddress((void**)&cl, g_cl);

    cudaFuncSetAttribute(gemm_tc, cudaFuncAttributeMaxDynamicSharedMemorySize, GEMM_SMEM);
    cudaFuncSetAttribute(attn_tc, cudaFuncAttributeMaxDynamicSharedMemorySize, ATTN_SMEM);

    const size_t WN = (size_t)EB * EB;
    const int xn4 = (MTOT * EB) / 4;
    const int wn4 = (int)(WN / 4);

    conv_split_kernel<<<(xn4 + 255) / 256, 256>>>(x, xh, xl, xn4);
    conv_cast_kernel<<<(wn4 + 255) / 256, 256>>>(Wq, wp + 0 * WN, wn4);
    conv_cast_kernel<<<(wn4 + 255) / 256, 256>>>(Wk, wp + 1 * WN, wn4);
    conv_cast_kernel<<<(wn4 + 255) / 256, 256>>>(Wv, wp + 2 * WN, wn4);
    conv_cast_kernel<<<(wn4 + 255) / 256, 256>>>(Wo, wp + 3 * WN, wn4);

    dim3 ggrid(EB / TN, MTOT / TM);   // (16, 32)
    // Q: single fp16 output
    gemm_tc<<<ggrid, 256, GEMM_SMEM>>>(xh, xl, wp + 0 * WN, bq,
                                       nullptr, qp, nullptr, MTOT, EB, EB);
    // K: single fp16 output
    gemm_tc<<<ggrid, 256, GEMM_SMEM>>>(xh, xl, wp + 1 * WN, bk,
                                       nullptr, kp, nullptr, MTOT, EB, EB);
    // V: exact split output
    gemm_tc<<<ggrid, 256, GEMM_SMEM>>>(xh, xl, wp + 2 * WN, bv,
                                       nullptr, vh, vl, MTOT, EB, EB);

    attn_tc<<<dim3(SB / AQ, BB * HH), 256, ATTN_SMEM>>>();

    // output projection: fp32 output
    gemm_tc<<<ggrid, 256, GEMM_SMEM>>>(ch, cl, wp + 3 * WN, bo,
                                       out, nullptr, nullptr, MTOT, EB, EB);
}

// round 8
// speedup vs baseline: 2.3376x; 1.4648x over previous
#include <cuda_runtime.h>
#include <cuda_fp16.h>
#include <cstdint>
#include <cstddef>

#define EB 2048
#define SB 2048
#define BB 2
#define HH 16
#define DH 128
#define MTOT (BB*SB)

// ---------------- scratch (device globals; no allocation) ----------------
__device__ __half g_x[(size_t)MTOT * EB];
__device__ __half g_w[(size_t)4 * EB * EB];
__device__ __half g_q[(size_t)MTOT * EB];
__device__ __half g_k[(size_t)MTOT * EB];
__device__ __half g_vh[(size_t)MTOT * EB];
__device__ __half g_vl[(size_t)MTOT * EB];
__device__ __half g_c[(size_t)MTOT * EB];

// ---------------- helpers ----------------
__device__ __forceinline__ uint32_t smem_u32(const void* p) {
    uint32_t a;
    asm("{ .reg .u64 t; cvta.to.shared.u64 t, %1; cvt.u32.u64 %0, t; }"
        : "=r"(a) : "l"(p));
    return a;
}

__device__ __forceinline__ void ldsm4(uint32_t* r, uint32_t a) {
    asm volatile("ldmatrix.sync.aligned.m8n8.x4.shared.b16 {%0,%1,%2,%3}, [%4];"
                 : "=r"(r[0]), "=r"(r[1]), "=r"(r[2]), "=r"(r[3]) : "r"(a));
}
__device__ __forceinline__ void ldsm4t(uint32_t* r, uint32_t a) {
    asm volatile("ldmatrix.sync.aligned.m8n8.x4.trans.shared.b16 {%0,%1,%2,%3}, [%4];"
                 : "=r"(r[0]), "=r"(r[1]), "=r"(r[2]), "=r"(r[3]) : "r"(a));
}

__device__ __forceinline__ void mma16816(float* d, const uint32_t* a, const uint32_t* b) {
    asm volatile(
        "mma.sync.aligned.m16n8k16.row.col.f32.f16.f16.f32 "
        "{%0,%1,%2,%3}, {%4,%5,%6,%7}, {%8,%9}, {%0,%1,%2,%3};"
        : "+f"(d[0]), "+f"(d[1]), "+f"(d[2]), "+f"(d[3])
        : "r"(a[0]), "r"(a[1]), "r"(a[2]), "r"(a[3]), "r"(b[0]), "r"(b[1]));
}

__device__ __forceinline__ void cp16(uint32_t dst, const void* src) {
    asm volatile("cp.async.cg.shared.global [%0], [%1], 16;" :: "r"(dst), "l"(src));
}
#define CP_COMMIT() asm volatile("cp.async.commit_group;" ::: "memory")
#define CP_WAIT1()  asm volatile("cp.async.wait_group 1;" ::: "memory")

__device__ __forceinline__ uint32_t pack_h(float lo, float hi) {
    __half2 t = __floats2half2_rn(lo, hi);
    return *reinterpret_cast<uint32_t*>(&t);
}
__device__ __forceinline__ float h_round(float v) {
    return __half2float(__float2half_rn(v));
}

// =========================================================================
// fp32 -> fp16 cast
// =========================================================================
__global__ void conv_cast_kernel(const float* __restrict__ in,
                                 __half* __restrict__ out, int n4)
{
    int i = blockIdx.x * blockDim.x + threadIdx.x;
    if (i >= n4) return;
    float4 v = reinterpret_cast<const float4*>(in)[i];
    uint2 H;
    H.x = pack_h(v.x, v.y); H.y = pack_h(v.z, v.w);
    reinterpret_cast<uint2*>(out)[i] = H;
}

// =========================================================================
// HMMA GEMM: C[M,N] = A[M,K] @ B[N,K]^T + bias[N]   (single fp16 terms)
// CTA 128x128, kc=32, 8 warps (2x4), warp tile 64x32, 2 CTAs/SM.
// Output modes: Cf (fp32) | Ch+Cl (split fp16) | Ch only (single fp16).
// =========================================================================
#define TM 128
#define TN 128
#define KC 32
#define GP 80                     // bytes/row in smem (64B data + 16B pad)
#define TILEB (128 * GP)          // 10240
#define STAGEB (2 * TILEB)        // A, B = 20480
#define GEMM_SMEM (2 * STAGEB)    // 40960

__device__ __forceinline__ void gemm_issue(
    const __half* s0, const __half* s1,
    int K, int k0, uint32_t base, int tid)
{
#pragma unroll
    for (int j = 0; j < 4; j++) {
        const int tile = j >> 1;
        const int part = (j & 1) * 256 + tid;   // 0..511
        const int r = part >> 2;
        const int c = part & 3;
        const __half* g = (tile == 0 ? s0 : s1) + (size_t)r * K + k0 + c * 8;
        cp16(base + tile * TILEB + r * GP + c * 16, g);
    }
}

__global__ __launch_bounds__(256, 2)
void gemm_tc(const __half* __restrict__ A, const __half* __restrict__ B,
             const float* __restrict__ bias,
             float* __restrict__ Cf,
             __half* __restrict__ Ch, __half* __restrict__ Cl,
             int M, int N, int K)
{
    extern __shared__ __align__(128) char smem[];
    const uint32_t sb = smem_u32(smem);
    const int tid = threadIdx.x, lane = tid & 31, wid = tid >> 5;
    const int wm = wid >> 2, wn = wid & 3;
    const int m0 = blockIdx.y * TM, n0 = blockIdx.x * TN;

    const __half* s0 = A + (size_t)m0 * K;
    const __half* s1 = B + (size_t)n0 * K;

    gemm_issue(s0, s1, K, 0, sb, tid);            CP_COMMIT();
    gemm_issue(s0, s1, K, KC, sb + STAGEB, tid);  CP_COMMIT();

    float acc[4][4][4];
#pragma unroll
    for (int a = 0; a < 4; a++)
#pragma unroll
        for (int b = 0; b < 4; b++)
#pragma unroll
            for (int c = 0; c < 4; c++) acc[a][b][c] = 0.f;

    const int arow = wm * 64 + (lane & 15);
    const uint32_t ak8 = ((lane >> 4) << 3) * 2;
    const int brow = wn * 32 + ((lane >> 4) << 3) + (lane & 7);
    const uint32_t bk8 = (((lane >> 3) & 1) << 3) * 2;

    const int niter = K / KC;   // 64
    for (int it = 0; it < niter; ++it) {
        CP_WAIT1();
        __syncthreads();
        const uint32_t st = sb + (it & 1) * STAGEB;
        const uint32_t a_s = st, b_s = st + TILEB;
#pragma unroll
        for (int ks = 0; ks < 2; ++ks) {
            uint32_t ah[4][4];
            const uint32_t ao = ak8 + ks * 32;
#pragma unroll
            for (int mt = 0; mt < 4; mt++)
                ldsm4(ah[mt], a_s + (uint32_t)(arow + mt * 16) * GP + ao);
#pragma unroll
            for (int np = 0; np < 2; np++) {
                uint32_t bh[4];
                uint32_t rb = (uint32_t)(brow + np * 16) * GP + bk8 + ks * 32;
                ldsm4(bh, b_s + rb);
#pragma unroll
                for (int mt = 0; mt < 4; mt++) {
                    mma16816(acc[mt][2 * np],     ah[mt], bh);
                    mma16816(acc[mt][2 * np + 1], ah[mt], bh + 2);
                }
            }
        }
        __syncthreads();
        if (it + 2 < niter)
            gemm_issue(s0, s1, K, (it + 2) * KC, sb + (it & 1) * STAGEB, tid);
        CP_COMMIT();
    }

    // epilogue
    const int g = lane >> 2, q = lane & 3;
#pragma unroll
    for (int mt = 0; mt < 4; mt++) {
        const int r0 = m0 + wm * 64 + mt * 16 + g;
        const int r1 = r0 + 8;
#pragma unroll
        for (int nt = 0; nt < 4; nt++) {
            const int c = n0 + wn * 32 + nt * 8 + q * 2;
            const float b0 = __ldg(bias + c), b1 = __ldg(bias + c + 1);
            const float v00 = acc[mt][nt][0] + b0, v01 = acc[mt][nt][1] + b1;
            const float v10 = acc[mt][nt][2] + b0, v11 = acc[mt][nt][3] + b1;
            if (Cf) {
                *reinterpret_cast<float2*>(Cf + (size_t)r0 * N + c) = make_float2(v00, v01);
                *reinterpret_cast<float2*>(Cf + (size_t)r1 * N + c) = make_float2(v10, v11);
            } else if (Cl) {
                const float h00 = h_round(v00), h01 = h_round(v01);
                const float h10 = h_round(v10), h11 = h_round(v11);
                *reinterpret_cast<uint32_t*>(Ch + (size_t)r0 * N + c) = pack_h(v00, v01);
                *reinterpret_cast<uint32_t*>(Cl + (size_t)r0 * N + c) = pack_h(v00 - h00, v01 - h01);
                *reinterpret_cast<uint32_t*>(Ch + (size_t)r1 * N + c) = pack_h(v10, v11);
                *reinterpret_cast<uint32_t*>(Cl + (size_t)r1 * N + c) = pack_h(v10 - h10, v11 - h11);
            } else {
                *reinterpret_cast<uint32_t*>(Ch + (size_t)r0 * N + c) = pack_h(v00, v01);
                *reinterpret_cast<uint32_t*>(Ch + (size_t)r1 * N + c) = pack_h(v10, v11);
            }
        }
    }
}

// =========================================================================
// Flash attention (causal), fp16 HMMA, cp.async KV double-buffer.
// Q,K,P single fp16; V exact split (vh+vl); ctx single fp16 out.
// CTA: 128 q x (b,h), 8 warps.
// =========================================================================
#define AQ 128
#define AKV 64
#define AP 272                      // bytes/row (256B data + 16B pad)
#define QSZ (128 * AP)              // 34816
#define KSZ (64 * AP)               // 17408
#define AKVB (3 * KSZ)              // one KV stage: K, Vh, Vl = 52224
#define ATTN_SMEM (QSZ + 2 * AKVB)  // 139264

__device__ __forceinline__ void attn_issue_kv(
    const __half* kg, const __half* vhg, const __half* vlg,
    int kv0, uint32_t dst, int tid)
{
#pragma unroll
    for (int j = 0; j < 12; j++) {
        const int arr = j >> 2;
        const int part = (j & 3) * 256 + tid;   // 0..1023
        const int r = part >> 4;
        const int c = part & 15;
        const __half* gp =
            (arr == 0 ? kg : arr == 1 ? vhg : vlg)
            + (size_t)(kv0 + r) * EB + c * 8;
        cp16(dst + arr * KSZ + r * AP + c * 16, gp);
    }
}

__global__ __launch_bounds__(256, 1)
void attn_tc()
{
    extern __shared__ __align__(128) char smem[];
    const uint32_t sb = smem_u32(smem);
    const uint32_t QS = sb, KVB = sb + QSZ;
    const int tid = threadIdx.x, lane = tid & 31, w = tid >> 5;
    const int qt = gridDim.x - 1 - blockIdx.x;      // big tiles first
    const int b  = blockIdx.y >> 4, h = blockIdx.y & 15;
    const int q0 = qt * AQ;
    const float scale = 0.08838834764831845f;       // 1/sqrt(128)

    const size_t hoff = (size_t)h * DH;
    const size_t bbase = (size_t)b * SB * EB + hoff;
    const __half* qg  = g_q  + bbase + (size_t)q0 * EB;
    const __half* kg  = g_k  + bbase;
    const __half* vhg = g_vh + bbase;
    const __half* vlg = g_vl + bbase;

    // prefetch KV tile 0 (stage 0)
    attn_issue_kv(kg, vhg, vlg, 0, KVB, tid);
    CP_COMMIT();

    // load Q (128 x 128 fp16) — overlaps with the cp.async above
#pragma unroll
    for (int j = 0; j < 8; j++) {
        const int part = j * 256 + tid;   // 0..2047
        const int r = part >> 4;
        const int c = part & 15;
        uint4 v = *reinterpret_cast<const uint4*>(qg + (size_t)r * EB + c * 8);
        *reinterpret_cast<uint4*>(smem + r * AP + c * 16) = v;
    }

    float o[16][4];
#pragma unroll
    for (int i = 0; i < 16; i++)
#pragma unroll
        for (int j = 0; j < 4; j++) o[i][j] = 0.f;
    float m0v = -1e30f, m1v = -1e30f, l0 = 0.f, l1 = 0.f;

    const int g = lane >> 2, q = lane & 3;
    const uint32_t a_row = (uint32_t)(w * 16 + (lane & 15)) * AP;
    const uint32_t a_k8  = ((lane >> 4) << 3) * 2;
    const int  k_row = ((lane >> 4) << 3) + (lane & 7);
    const uint32_t k_k8 = (((lane >> 3) & 1) << 3) * 2;
    const int  v_row = (((lane >> 3) & 1) << 3) + (lane & 7);
    const uint32_t v_d8 = ((lane >> 4) << 3) * 2;

    const int ntiles = 2 * qt + 2;
    for (int kti = 0; kti < ntiles; ++kti) {
        const int kv0 = kti * AKV;
        __syncthreads();   // all readers done with the stage we write next
        if (kti + 1 < ntiles)
            attn_issue_kv(kg, vhg, vlg, (kti + 1) * AKV,
                          KVB + ((kti + 1) & 1) * AKVB, tid);
        CP_COMMIT();
        CP_WAIT1();        // tile kti complete
        __syncthreads();

        if (kv0 > q0 + w * 16 + 15) continue;     // whole warp masked

        const uint32_t ST = KVB + (kti & 1) * AKVB;

        // ---- S = Q K^T  (single fp16 both sides) ----
        float s[8][4];
#pragma unroll
        for (int i = 0; i < 8; i++)
#pragma unroll
            for (int j = 0; j < 4; j++) s[i][j] = 0.f;

#pragma unroll
        for (int ks = 0; ks < 8; ks++) {
            uint32_t aq[4];
            ldsm4(aq, QS + a_row + a_k8 + ks * 32);
#pragma unroll
            for (int ntp = 0; ntp < 4; ntp++) {
                uint32_t bh[4];
                const uint32_t ra = (uint32_t)(k_row + ntp * 16) * AP + k_k8 + ks * 32;
                ldsm4(bh, ST + ra);
                mma16816(s[2 * ntp],     aq, bh);
                mma16816(s[2 * ntp + 1], aq, bh + 2);
            }
        }

        // ---- scale + causal mask ----
        const int r0g = q0 + w * 16 + g, r1g = r0g + 8;
        const bool needmask = (kv0 + AKV - 1) > (q0 + w * 16);
#pragma unroll
        for (int nt = 0; nt < 8; nt++) {
            const int c0 = kv0 + nt * 8 + q * 2;
            s[nt][0] *= scale; s[nt][1] *= scale; s[nt][2] *= scale; s[nt][3] *= scale;
            if (needmask) {
                if (c0     > r0g) s[nt][0] = -1e30f;
                if (c0 + 1 > r0g) s[nt][1] = -1e30f;
                if (c0     > r1g) s[nt][2] = -1e30f;
                if (c0 + 1 > r1g) s[nt][3] = -1e30f;
            }
        }

        // ---- online softmax (rows r0g, r1g) ----
        float mx0 = -1e30f, mx1 = -1e30f;
#pragma unroll
        for (int nt = 0; nt < 8; nt++) {
            mx0 = fmaxf(mx0, fmaxf(s[nt][0], s[nt][1]));
            mx1 = fmaxf(mx1, fmaxf(s[nt][2], s[nt][3]));
        }
        mx0 = fmaxf(mx0, __shfl_xor_sync(0xffffffffu, mx0, 1));
        mx0 = fmaxf(mx0, __shfl_xor_sync(0xffffffffu, mx0, 2));
        mx1 = fmaxf(mx1, __shfl_xor_sync(0xffffffffu, mx1, 1));
        mx1 = fmaxf(mx1, __shfl_xor_sync(0xffffffffu, mx1, 2));

        const float mn0 = fmaxf(m0v, mx0), mn1 = fmaxf(m1v, mx1);
        const float al0 = __expf(m0v - mn0), al1 = __expf(m1v - mn1);
        m0v = mn0; m1v = mn1;
        float rs0 = 0.f, rs1 = 0.f;
#pragma unroll
        for (int nt = 0; nt < 8; nt++) {
            s[nt][0] = __expf(s[nt][0] - mn0); rs0 += s[nt][0];
            s[nt][1] = __expf(s[nt][1] - mn0); rs0 += s[nt][1];
            s[nt][2] = __expf(s[nt][2] - mn1); rs1 += s[nt][2];
            s[nt][3] = __expf(s[nt][3] - mn1); rs1 += s[nt][3];
        }
        rs0 += __shfl_xor_sync(0xffffffffu, rs0, 1);
        rs0 += __shfl_xor_sync(0xffffffffu, rs0, 2);
        rs1 += __shfl_xor_sync(0xffffffffu, rs1, 1);
        rs1 += __shfl_xor_sync(0xffffffffu, rs1, 2);
        l0 = l0 * al0 + rs0;
        l1 = l1 * al1 + rs1;
#pragma unroll
        for (int nt = 0; nt < 16; nt++) {
            o[nt][0] *= al0; o[nt][1] *= al0; o[nt][2] *= al1; o[nt][3] *= al1;
        }

        // ---- O += P @ (Vh + Vl)  (P single fp16, V exact split) ----
#pragma unroll
        for (int kt = 0; kt < 4; kt++) {
            uint32_t ph[4];
            const float* p0 = s[2 * kt];
            const float* p1 = s[2 * kt + 1];
            ph[0] = pack_h(p0[0], p0[1]);
            ph[1] = pack_h(p0[2], p0[3]);
            ph[2] = pack_h(p1[0], p1[1]);
            ph[3] = pack_h(p1[2], p1[3]);
#pragma unroll
            for (int np = 0; np < 8; np++) {
                uint32_t vh[4], vl[4];
                const uint32_t ra = (uint32_t)(v_row + kt * 16) * AP + v_d8 + np * 32;
                ldsm4t(vh, ST + 1 * KSZ + ra);
                ldsm4t(vl, ST + 2 * KSZ + ra);
                mma16816(o[2 * np],     ph, vh);
                mma16816(o[2 * np],     ph, vl);
                mma16816(o[2 * np + 1], ph, vh + 2);
                mma16816(o[2 * np + 1], ph, vl + 2);
            }
        }
    }

    // ---- normalize + write single-fp16 ctx ----
    const float inv0 = 1.f / l0, inv1 = 1.f / l1;
    const int r0g = q0 + w * 16 + g;
    const size_t base0 = ((size_t)b * SB + r0g) * EB + hoff;
    const size_t base1 = base0 + (size_t)8 * EB;
#pragma unroll
    for (int nt = 0; nt < 16; nt++) {
        const int c = nt * 8 + q * 2;
        *reinterpret_cast<uint32_t*>(g_c + base0 + c) =
            pack_h(o[nt][0] * inv0, o[nt][1] * inv0);
        *reinterpret_cast<uint32_t*>(g_c + base1 + c) =
            pack_h(o[nt][2] * inv1, o[nt][3] * inv1);
    }
}

// =========================================================================
extern "C" void kernel_launch(void* const* d_in, const int* in_sizes, int n_in,
                              void* d_out, int out_size)
{
    const float* x  = (const float*)d_in[0];
    const float* Wq = (const float*)d_in[1];
    const float* bq = (const float*)d_in[2];
    const float* Wk = (const float*)d_in[3];
    const float* bk = (const float*)d_in[4];
    const float* Wv = (const float*)d_in[5];
    const float* bv = (const float*)d_in[6];
    const float* Wo = (const float*)d_in[7];
    const float* bo = (const float*)d_in[8];
    float* out = (float*)d_out;

    __half *xp, *wp, *qp, *kp, *vh, *vl, *cp;
    cudaGetSymbolAddress((void**)&xp, g_x);
    cudaGetSymbolAddress((void**)&wp, g_w);
    cudaGetSymbolAddress((void**)&qp, g_q);
    cudaGetSymbolAddress((void**)&kp, g_k);
    cudaGetSymbolAddress((void**)&vh, g_vh);
    cudaGetSymbolAddress((void**)&vl, g_vl);
    cudaGetSymbolAddress((void**)&cp, g_c);

    cudaFuncSetAttribute(gemm_tc, cudaFuncAttributeMaxDynamicSharedMemorySize, GEMM_SMEM);
    cudaFuncSetAttribute(attn_tc, cudaFuncAttributeMaxDynamicSharedMemorySize, ATTN_SMEM);

    const size_t WN = (size_t)EB * EB;
    const int xn4 = (MTOT * EB) / 4;
    const int wn4 = (int)(WN / 4);

    conv_cast_kernel<<<(xn4 + 255) / 256, 256>>>(x, xp, xn4);
    conv_cast_kernel<<<(wn4 + 255) / 256, 256>>>(Wq, wp + 0 * WN, wn4);
    conv_cast_kernel<<<(wn4 + 255) / 256, 256>>>(Wk, wp + 1 * WN, wn4);
    conv_cast_kernel<<<(wn4 + 255) / 256, 256>>>(Wv, wp + 2 * WN, wn4);
    conv_cast_kernel<<<(wn4 + 255) / 256, 256>>>(Wo, wp + 3 * WN, wn4);

    dim3 ggrid(EB / TN, MTOT / TM);   // (16, 32)
    // Q: single fp16 output
    gemm_tc<<<ggrid, 256, GEMM_SMEM>>>(xp, wp + 0 * WN, bq,
                                       nullptr, qp, nullptr, MTOT, EB, EB);
    // K: single fp16 output
    gemm_tc<<<ggrid, 256, GEMM_SMEM>>>(xp, wp + 1 * WN, bk,
                                       nullptr, kp, nullptr, MTOT, EB, EB);
    // V: exact split output
    gemm_tc<<<ggrid, 256, GEMM_SMEM>>>(xp, wp + 2 * WN, bv,
                                       nullptr, vh, vl, MTOT, EB, EB);

    attn_tc<<<dim3(SB / AQ, BB * HH), 256, ATTN_SMEM>>>();

    // output projection: fp32 output
    gemm_tc<<<ggrid, 256, GEMM_SMEM>>>(cp, wp + 3 * WN, bo,
                                       out, nullptr, nullptr, MTOT, EB, EB);
}

// round 10
// speedup vs baseline: 2.3389x; 1.0006x over previous
#include <cuda_runtime.h>
#include <cuda_fp16.h>
#include <cstdint>
#include <cstddef>

#define EB 2048
#define SB 2048
#define BB 2
#define HH 16
#define DH 128
#define MTOT (BB*SB)

// ---------------- scratch (device globals; no allocation) ----------------
__device__ __half g_x[(size_t)MTOT * EB];
__device__ __half g_w[(size_t)4 * EB * EB];
__device__ __half g_q[(size_t)MTOT * EB];
__device__ __half g_k[(size_t)MTOT * EB];
__device__ __half g_vh[(size_t)MTOT * EB];
__device__ __half g_vl[(size_t)MTOT * EB];
__device__ __half g_c[(size_t)MTOT * EB];

// ---------------- helpers ----------------
__device__ __forceinline__ uint32_t smem_u32(const void* p) {
    uint32_t a;
    asm("{ .reg .u64 t; cvta.to.shared.u64 t, %1; cvt.u32.u64 %0, t; }"
        : "=r"(a) : "l"(p));
    return a;
}

__device__ __forceinline__ void ldsm4(uint32_t* r, uint32_t a) {
    asm volatile("ldmatrix.sync.aligned.m8n8.x4.shared.b16 {%0,%1,%2,%3}, [%4];"
                 : "=r"(r[0]), "=r"(r[1]), "=r"(r[2]), "=r"(r[3]) : "r"(a));
}
__device__ __forceinline__ void ldsm4t(uint32_t* r, uint32_t a) {
    asm volatile("ldmatrix.sync.aligned.m8n8.x4.trans.shared.b16 {%0,%1,%2,%3}, [%4];"
                 : "=r"(r[0]), "=r"(r[1]), "=r"(r[2]), "=r"(r[3]) : "r"(a));
}

__device__ __forceinline__ void mma16816(float* d, const uint32_t* a, const uint32_t* b) {
    asm volatile(
        "mma.sync.aligned.m16n8k16.row.col.f32.f16.f16.f32 "
        "{%0,%1,%2,%3}, {%4,%5,%6,%7}, {%8,%9}, {%0,%1,%2,%3};"
        : "+f"(d[0]), "+f"(d[1]), "+f"(d[2]), "+f"(d[3])
        : "r"(a[0]), "r"(a[1]), "r"(a[2]), "r"(a[3]), "r"(b[0]), "r"(b[1]));
}

__device__ __forceinline__ void cp16(uint32_t dst, const void* src) {
    asm volatile("cp.async.cg.shared.global [%0], [%1], 16;" :: "r"(dst), "l"(src));
}
#define CP_COMMIT() asm volatile("cp.async.commit_group;" ::: "memory")
#define CP_WAIT1()  asm volatile("cp.async.wait_group 1;" ::: "memory")

__device__ __forceinline__ uint32_t pack_h(float lo, float hi) {
    __half2 t = __floats2half2_rn(lo, hi);
    return *reinterpret_cast<uint32_t*>(&t);
}
__device__ __forceinline__ float h_round(float v) {
    return __half2float(__float2half_rn(v));
}

// =========================================================================
// fp32 -> fp16 cast
// =========================================================================
__global__ void conv_cast_kernel(const float* __restrict__ in,
                                 __half* __restrict__ out, int n4)
{
    int i = blockIdx.x * blockDim.x + threadIdx.x;
    if (i >= n4) return;
    float4 v = reinterpret_cast<const float4*>(in)[i];
    uint2 H;
    H.x = pack_h(v.x, v.y); H.y = pack_h(v.z, v.w);
    reinterpret_cast<uint2*>(out)[i] = H;
}

// =========================================================================
// HMMA GEMM: C[M,N] = A[M,K] @ B[N,K]^T + bias[N]   (single fp16 terms)
// CTA 128x128, kc=32, 8 warps (2x4), warp tile 64x32, 2 CTAs/SM.
// Output modes: Cf (fp32) | Ch+Cl (split fp16) | Ch only (single fp16).
// =========================================================================
#define TM 128
#define TN 128
#define KC 32
#define GP 80                     // bytes/row in smem (64B data + 16B pad)
#define TILEB (128 * GP)          // 10240
#define STAGEB (2 * TILEB)        // A, B = 20480
#define GEMM_SMEM (2 * STAGEB)    // 40960

__device__ __forceinline__ void gemm_issue(
    const __half* s0, const __half* s1,
    int K, int k0, uint32_t base, int tid)
{
#pragma unroll
    for (int j = 0; j < 4; j++) {
        const int tile = j >> 1;
        const int part = (j & 1) * 256 + tid;   // 0..511
        const int r = part >> 2;
        const int c = part & 3;
        const __half* g = (tile == 0 ? s0 : s1) + (size_t)r * K + k0 + c * 8;
        cp16(base + tile * TILEB + r * GP + c * 16, g);
    }
}

__global__ __launch_bounds__(256, 2)
void gemm_tc(const __half* __restrict__ A, const __half* __restrict__ B,
             const float* __restrict__ bias,
             float* __restrict__ Cf,
             __half* __restrict__ Ch, __half* __restrict__ Cl,
             int M, int N, int K)
{
    extern __shared__ __align__(128) char smem[];
    const uint32_t sb = smem_u32(smem);
    const int tid = threadIdx.x, lane = tid & 31, wid = tid >> 5;
    const int wm = wid >> 2, wn = wid & 3;
    const int m0 = blockIdx.y * TM, n0 = blockIdx.x * TN;

    const __half* s0 = A + (size_t)m0 * K;
    const __half* s1 = B + (size_t)n0 * K;

    gemm_issue(s0, s1, K, 0, sb, tid);            CP_COMMIT();
    gemm_issue(s0, s1, K, KC, sb + STAGEB, tid);  CP_COMMIT();

    float acc[4][4][4];
#pragma unroll
    for (int a = 0; a < 4; a++)
#pragma unroll
        for (int b = 0; b < 4; b++)
#pragma unroll
            for (int c = 0; c < 4; c++) acc[a][b][c] = 0.f;

    const int arow = wm * 64 + (lane & 15);
    const uint32_t ak8 = ((lane >> 4) << 3) * 2;
    const int brow = wn * 32 + ((lane >> 4) << 3) + (lane & 7);
    const uint32_t bk8 = (((lane >> 3) & 1) << 3) * 2;

    const int niter = K / KC;   // 64
    for (int it = 0; it < niter; ++it) {
        CP_WAIT1();
        __syncthreads();
        const uint32_t st = sb + (it & 1) * STAGEB;
        const uint32_t a_s = st, b_s = st + TILEB;
#pragma unroll
        for (int ks = 0; ks < 2; ++ks) {
            uint32_t ah[4][4];
            const uint32_t ao = ak8 + ks * 32;
#pragma unroll
            for (int mt = 0; mt < 4; mt++)
                ldsm4(ah[mt], a_s + (uint32_t)(arow + mt * 16) * GP + ao);
#pragma unroll
            for (int np = 0; np < 2; np++) {
                uint32_t bh[4];
                uint32_t rb = (uint32_t)(brow + np * 16) * GP + bk8 + ks * 32;
                ldsm4(bh, b_s + rb);
#pragma unroll
                for (int mt = 0; mt < 4; mt++) {
                    mma16816(acc[mt][2 * np],     ah[mt], bh);
                    mma16816(acc[mt][2 * np + 1], ah[mt], bh + 2);
                }
            }
        }
        __syncthreads();
        if (it + 2 < niter)
            gemm_issue(s0, s1, K, (it + 2) * KC, sb + (it & 1) * STAGEB, tid);
        CP_COMMIT();
    }

    // epilogue
    const int g = lane >> 2, q = lane & 3;
#pragma unroll
    for (int mt = 0; mt < 4; mt++) {
        const int r0 = m0 + wm * 64 + mt * 16 + g;
        const int r1 = r0 + 8;
#pragma unroll
        for (int nt = 0; nt < 4; nt++) {
            const int c = n0 + wn * 32 + nt * 8 + q * 2;
            const float b0 = __ldg(bias + c), b1 = __ldg(bias + c + 1);
            const float v00 = acc[mt][nt][0] + b0, v01 = acc[mt][nt][1] + b1;
            const float v10 = acc[mt][nt][2] + b0, v11 = acc[mt][nt][3] + b1;
            if (Cf) {
                *reinterpret_cast<float2*>(Cf + (size_t)r0 * N + c) = make_float2(v00, v01);
                *reinterpret_cast<float2*>(Cf + (size_t)r1 * N + c) = make_float2(v10, v11);
            } else if (Cl) {
                const float h00 = h_round(v00), h01 = h_round(v01);
                const float h10 = h_round(v10), h11 = h_round(v11);
                *reinterpret_cast<uint32_t*>(Ch + (size_t)r0 * N + c) = pack_h(v00, v01);
                *reinterpret_cast<uint32_t*>(Cl + (size_t)r0 * N + c) = pack_h(v00 - h00, v01 - h01);
                *reinterpret_cast<uint32_t*>(Ch + (size_t)r1 * N + c) = pack_h(v10, v11);
                *reinterpret_cast<uint32_t*>(Cl + (size_t)r1 * N + c) = pack_h(v10 - h10, v11 - h11);
            } else {
                *reinterpret_cast<uint32_t*>(Ch + (size_t)r0 * N + c) = pack_h(v00, v01);
                *reinterpret_cast<uint32_t*>(Ch + (size_t)r1 * N + c) = pack_h(v10, v11);
            }
        }
    }
}

// =========================================================================
// Flash attention (causal), fp16 HMMA, cp.async KV double-buffer.
// Q,K,P single fp16; V exact split (vh+vl); ctx single fp16 out.
// CTA: 128 q x (b,h), 8 warps.
// =========================================================================
#define AQ 128
#define AKV 64
#define AP 272                      // bytes/row (256B data + 16B pad)
#define QSZ (128 * AP)              // 34816
#define KSZ (64 * AP)               // 17408
#define AKVB (3 * KSZ)              // one KV stage: K, Vh, Vl = 52224
#define ATTN_SMEM (QSZ + 2 * AKVB)  // 139264

__device__ __forceinline__ void attn_issue_kv(
    const __half* kg, const __half* vhg, const __half* vlg,
    int kv0, uint32_t dst, int tid)
{
#pragma unroll
    for (int j = 0; j < 12; j++) {
        const int arr = j >> 2;
        const int part = (j & 3) * 256 + tid;   // 0..1023
        const int r = part >> 4;
        const int c = part & 15;
        const __half* gp =
            (arr == 0 ? kg : arr == 1 ? vhg : vlg)
            + (size_t)(kv0 + r) * EB + c * 8;
        cp16(dst + arr * KSZ + r * AP + c * 16, gp);
    }
}

__global__ __launch_bounds__(256, 1)
void attn_tc()
{
    extern __shared__ __align__(128) char smem[];
    const uint32_t sb = smem_u32(smem);
    const uint32_t QS = sb, KVB = sb + QSZ;
    const int tid = threadIdx.x, lane = tid & 31, w = tid >> 5;
    const int qt = gridDim.x - 1 - blockIdx.x;      // big tiles first
    const int b  = blockIdx.y >> 4, h = blockIdx.y & 15;
    const int q0 = qt * AQ;
    const float scale = 0.08838834764831845f;       // 1/sqrt(128)

    const size_t hoff = (size_t)h * DH;
    const size_t bbase = (size_t)b * SB * EB + hoff;
    const __half* qg  = g_q  + bbase + (size_t)q0 * EB;
    const __half* kg  = g_k  + bbase;
    const __half* vhg = g_vh + bbase;
    const __half* vlg = g_vl + bbase;

    // prefetch KV tile 0 (stage 0)
    attn_issue_kv(kg, vhg, vlg, 0, KVB, tid);
    CP_COMMIT();

    // load Q (128 x 128 fp16) — overlaps with the cp.async above
#pragma unroll
    for (int j = 0; j < 8; j++) {
        const int part = j * 256 + tid;   // 0..2047
        const int r = part >> 4;
        const int c = part & 15;
        uint4 v = *reinterpret_cast<const uint4*>(qg + (size_t)r * EB + c * 8);
        *reinterpret_cast<uint4*>(smem + r * AP + c * 16) = v;
    }

    float o[16][4];
#pragma unroll
    for (int i = 0; i < 16; i++)
#pragma unroll
        for (int j = 0; j < 4; j++) o[i][j] = 0.f;
    float m0v = -1e30f, m1v = -1e30f, l0 = 0.f, l1 = 0.f;

    const int g = lane >> 2, q = lane & 3;
    const uint32_t a_row = (uint32_t)(w * 16 + (lane & 15)) * AP;
    const uint32_t a_k8  = ((lane >> 4) << 3) * 2;
    const int  k_row = ((lane >> 4) << 3) + (lane & 7);
    const uint32_t k_k8 = (((lane >> 3) & 1) << 3) * 2;
    const int  v_row = (((lane >> 3) & 1) << 3) + (lane & 7);
    const uint32_t v_d8 = ((lane >> 4) << 3) * 2;

    const int ntiles = 2 * qt + 2;
    for (int kti = 0; kti < ntiles; ++kti) {
        const int kv0 = kti * AKV;
        __syncthreads();   // all readers done with the stage we write next
        if (kti + 1 < ntiles)
            attn_issue_kv(kg, vhg, vlg, (kti + 1) * AKV,
                          KVB + ((kti + 1) & 1) * AKVB, tid);
        CP_COMMIT();
        CP_WAIT1();        // tile kti complete
        __syncthreads();

        if (kv0 > q0 + w * 16 + 15) continue;     // whole warp masked

        const uint32_t ST = KVB + (kti & 1) * AKVB;

        // ---- S = Q K^T  (single fp16 both sides) ----
        float s[8][4];
#pragma unroll
        for (int i = 0; i < 8; i++)
#pragma unroll
            for (int j = 0; j < 4; j++) s[i][j] = 0.f;

#pragma unroll
        for (int ks = 0; ks < 8; ks++) {
            uint32_t aq[4];
            ldsm4(aq, QS + a_row + a_k8 + ks * 32);
#pragma unroll
            for (int ntp = 0; ntp < 4; ntp++) {
                uint32_t bh[4];
                const uint32_t ra = (uint32_t)(k_row + ntp * 16) * AP + k_k8 + ks * 32;
                ldsm4(bh, ST + ra);
                mma16816(s[2 * ntp],     aq, bh);
                mma16816(s[2 * ntp + 1], aq, bh + 2);
            }
        }

        // ---- scale + causal mask ----
        const int r0g = q0 + w * 16 + g, r1g = r0g + 8;
        const bool needmask = (kv0 + AKV - 1) > (q0 + w * 16);
#pragma unroll
        for (int nt = 0; nt < 8; nt++) {
            const int c0 = kv0 + nt * 8 + q * 2;
            s[nt][0] *= scale; s[nt][1] *= scale; s[nt][2] *= scale; s[nt][3] *= scale;
            if (needmask) {
                if (c0     > r0g) s[nt][0] = -1e30f;
                if (c0 + 1 > r0g) s[nt][1] = -1e30f;
                if (c0     > r1g) s[nt][2] = -1e30f;
                if (c0 + 1 > r1g) s[nt][3] = -1e30f;
            }
        }

        // ---- online softmax (rows r0g, r1g) ----
        float mx0 = -1e30f, mx1 = -1e30f;
#pragma unroll
        for (int nt = 0; nt < 8; nt++) {
            mx0 = fmaxf(mx0, fmaxf(s[nt][0], s[nt][1]));
            mx1 = fmaxf(mx1, fmaxf(s[nt][2], s[nt][3]));
        }
        mx0 = fmaxf(mx0, __shfl_xor_sync(0xffffffffu, mx0, 1));
        mx0 = fmaxf(mx0, __shfl_xor_sync(0xffffffffu, mx0, 2));
        mx1 = fmaxf(mx1, __shfl_xor_sync(0xffffffffu, mx1, 1));
        mx1 = fmaxf(mx1, __shfl_xor_sync(0xffffffffu, mx1, 2));

        const float mn0 = fmaxf(m0v, mx0), mn1 = fmaxf(m1v, mx1);
        const float al0 = __expf(m0v - mn0), al1 = __expf(m1v - mn1);
        m0v = mn0; m1v = mn1;
        float rs0 = 0.f, rs1 = 0.f;
#pragma unroll
        for (int nt = 0; nt < 8; nt++) {
            s[nt][0] = __expf(s[nt][0] - mn0); rs0 += s[nt][0];
            s[nt][1] = __expf(s[nt][1] - mn0); rs0 += s[nt][1];
            s[nt][2] = __expf(s[nt][2] - mn1); rs1 += s[nt][2];
            s[nt][3] = __expf(s[nt][3] - mn1); rs1 += s[nt][3];
        }
        rs0 += __shfl_xor_sync(0xffffffffu, rs0, 1);
        rs0 += __shfl_xor_sync(0xffffffffu, rs0, 2);
        rs1 += __shfl_xor_sync(0xffffffffu, rs1, 1);
        rs1 += __shfl_xor_sync(0xffffffffu, rs1, 2);
        l0 = l0 * al0 + rs0;
        l1 = l1 * al1 + rs1;
#pragma unroll
        for (int nt = 0; nt < 16; nt++) {
            o[nt][0] *= al0; o[nt][1] *= al0; o[nt][2] *= al1; o[nt][3] *= al1;
        }

        // ---- O += P @ (Vh + Vl)  (P single fp16, V exact split) ----
#pragma unroll
        for (int kt = 0; kt < 4; kt++) {
            uint32_t ph[4];
            const float* p0 = s[2 * kt];
            const float* p1 = s[2 * kt + 1];
            ph[0] = pack_h(p0[0], p0[1]);
            ph[1] = pack_h(p0[2], p0[3]);
            ph[2] = pack_h(p1[0], p1[1]);
            ph[3] = pack_h(p1[2], p1[3]);
#pragma unroll
            for (int np = 0; np < 8; np++) {
                uint32_t vh[4], vl[4];
                const uint32_t ra = (uint32_t)(v_row + kt * 16) * AP + v_d8 + np * 32;
                ldsm4t(vh, ST + 1 * KSZ + ra);
                ldsm4t(vl, ST + 2 * KSZ + ra);
                mma16816(o[2 * np],     ph, vh);
                mma16816(o[2 * np],     ph, vl);
                mma16816(o[2 * np + 1], ph, vh + 2);
                mma16816(o[2 * np + 1], ph, vl + 2);
            }
        }
    }

    // ---- normalize + write single-fp16 ctx ----
    const float inv0 = 1.f / l0, inv1 = 1.f / l1;
    const int r0g = q0 + w * 16 + g;
    const size_t base0 = ((size_t)b * SB + r0g) * EB + hoff;
    const size_t base1 = base0 + (size_t)8 * EB;
#pragma unroll
    for (int nt = 0; nt < 16; nt++) {
        const int c = nt * 8 + q * 2;
        *reinterpret_cast<uint32_t*>(g_c + base0 + c) =
            pack_h(o[nt][0] * inv0, o[nt][1] * inv0);
        *reinterpret_cast<uint32_t*>(g_c + base1 + c) =
            pack_h(o[nt][2] * inv1, o[nt][3] * inv1);
    }
}

// =========================================================================
extern "C" void kernel_launch(void* const* d_in, const int* in_sizes, int n_in,
                              void* d_out, int out_size)
{
    const float* x  = (const float*)d_in[0];
    const float* Wq = (const float*)d_in[1];
    const float* bq = (const float*)d_in[2];
    const float* Wk = (const float*)d_in[3];
    const float* bk = (const float*)d_in[4];
    const float* Wv = (const float*)d_in[5];
    const float* bv = (const float*)d_in[6];
    const float* Wo = (const float*)d_in[7];
    const float* bo = (const float*)d_in[8];
    float* out = (float*)d_out;

    __half *xp, *wp, *qp, *kp, *vh, *vl, *cp;
    cudaGetSymbolAddress((void**)&xp, g_x);
    cudaGetSymbolAddress((void**)&wp, g_w);
    cudaGetSymbolAddress((void**)&qp, g_q);
    cudaGetSymbolAddress((void**)&kp, g_k);
    cudaGetSymbolAddress((void**)&vh, g_vh);
    cudaGetSymbolAddress((void**)&vl, g_vl);
    cudaGetSymbolAddress((void**)&cp, g_c);

    cudaFuncSetAttribute(gemm_tc, cudaFuncAttributeMaxDynamicSharedMemorySize, GEMM_SMEM);
    cudaFuncSetAttribute(attn_tc, cudaFuncAttributeMaxDynamicSharedMemorySize, ATTN_SMEM);

    const size_t WN = (size_t)EB * EB;
    const int xn4 = (MTOT * EB) / 4;
    const int wn4 = (int)(WN / 4);

    conv_cast_kernel<<<(xn4 + 255) / 256, 256>>>(x, xp, xn4);
    conv_cast_kernel<<<(wn4 + 255) / 256, 256>>>(Wq, wp + 0 * WN, wn4);
    conv_cast_kernel<<<(wn4 + 255) / 256, 256>>>(Wk, wp + 1 * WN, wn4);
    conv_cast_kernel<<<(wn4 + 255) / 256, 256>>>(Wv, wp + 2 * WN, wn4);
    conv_cast_kernel<<<(wn4 + 255) / 256, 256>>>(Wo, wp + 3 * WN, wn4);

    dim3 ggrid(EB / TN, MTOT / TM);   // (16, 32)
    // Q: single fp16 output
    gemm_tc<<<ggrid, 256, GEMM_SMEM>>>(xp, wp + 0 * WN, bq,
                                       nullptr, qp, nullptr, MTOT, EB, EB);
    // K: single fp16 output
    gemm_tc<<<ggrid, 256, GEMM_SMEM>>>(xp, wp + 1 * WN, bk,
                                       nullptr, kp, nullptr, MTOT, EB, EB);
    // V: exact split output
    gemm_tc<<<ggrid, 256, GEMM_SMEM>>>(xp, wp + 2 * WN, bv,
                                       nullptr, vh, vl, MTOT, EB, EB);

    attn_tc<<<dim3(SB / AQ, BB * HH), 256, ATTN_SMEM>>>();

    // output projection: fp32 output
    gemm_tc<<<ggrid, 256, GEMM_SMEM>>>(cp, wp + 3 * WN, bo,
                                       out, nullptr, nullptr, MTOT, EB, EB);
}